// round 15
// baseline (speedup 1.0000x reference)
#include <cuda_runtime.h>
#include <cuda_fp16.h>
#include <cstdint>

#define D_IN  4096
#define D_OUT 4096
#define M_TOT 16384
constexpr int RANK = 16;

// ---------------------------------------------------------------------------
// Scratch: fp16 copies of x and K^T
// ---------------------------------------------------------------------------
__device__ __half g_x16[(size_t)M_TOT * D_IN];     // [M,K] K-contig, 128 MB
__device__ __half g_k16[(size_t)D_OUT * D_IN];     // K^T [N,K] K-contig, 32 MB

// ---------------------------------------------------------------------------
// Helpers
// ---------------------------------------------------------------------------
__device__ __forceinline__ uint32_t smem_u32(const void* p) {
    return (uint32_t)__cvta_generic_to_shared(p);
}
__device__ __forceinline__ void cp16(uint32_t s, const void* g) {
    asm volatile("cp.async.cg.shared.global [%0], [%1], 16;\n" :: "r"(s), "l"(g));
}
#define CP_COMMIT() asm volatile("cp.async.commit_group;\n")
#define CP_WAIT1()  asm volatile("cp.async.wait_group 1;\n")

__device__ __forceinline__ void ldsm_x4(uint32_t& r0, uint32_t& r1, uint32_t& r2,
                                        uint32_t& r3, uint32_t a) {
    asm volatile("ldmatrix.sync.aligned.m8n8.x4.shared.b16 {%0,%1,%2,%3}, [%4];\n"
                 : "=r"(r0), "=r"(r1), "=r"(r2), "=r"(r3) : "r"(a));
}
__device__ __forceinline__ void mma16816(float* c, const uint32_t* a, const uint32_t* b) {
    asm volatile(
        "mma.sync.aligned.m16n8k16.row.col.f32.f16.f16.f32 "
        "{%0,%1,%2,%3}, {%4,%5,%6,%7}, {%8,%9}, {%0,%1,%2,%3};\n"
        : "+f"(c[0]), "+f"(c[1]), "+f"(c[2]), "+f"(c[3])
        : "r"(a[0]), "r"(a[1]), "r"(a[2]), "r"(a[3]), "r"(b[0]), "r"(b[1]));
}

// SW128 swizzle on byte offsets within a tile (128-byte rows)
__device__ __forceinline__ uint32_t swz(uint32_t b) { return b ^ ((b >> 3) & 0x70); }

// ---------------------------------------------------------------------------
// Combined aux kernel: one launch, blockIdx-partitioned.
//   blocks [0, NB_CVT)           : x fp32 -> fp16 (8 elems/thread)
//   blocks [NB_CVT, NB_CVT+NB_K) : build K^T fp16 (32x32 transpose tiles)
// Both DRAM-bound; one launch lets the two phases' waves overlap.
// ---------------------------------------------------------------------------
constexpr int NB_CVT = (int)(((size_t)M_TOT * D_IN) / 8 / 256);   // 32768
constexpr int NB_K   = (D_OUT / 32) * (D_IN / 32);                // 16384

__global__ void __launch_bounds__(256)
aux_kernel(const float4* __restrict__ x, const float* __restrict__ W,
           const float* __restrict__ a0, const float* __restrict__ b0,
           const float* __restrict__ a1, const float* __restrict__ b1) {
    if (blockIdx.x < NB_CVT) {
        size_t i = (size_t)blockIdx.x * 256 + threadIdx.x;
        float4 v0 = x[2 * i], v1 = x[2 * i + 1];
        union { __half h[8]; uint4 u; } o;
        o.h[0] = __float2half_rn(v0.x); o.h[1] = __float2half_rn(v0.y);
        o.h[2] = __float2half_rn(v0.z); o.h[3] = __float2half_rn(v0.w);
        o.h[4] = __float2half_rn(v1.x); o.h[5] = __float2half_rn(v1.y);
        o.h[6] = __float2half_rn(v1.z); o.h[7] = __float2half_rn(v1.w);
        reinterpret_cast<uint4*>(g_x16)[i] = o.u;
        return;
    }
    // build_k: K = W + (1/256)(a0@b0)⊙(a1@b1), transposed into g_k16[n][k].
    // 256 threads per 32x32 tile, each thread computes 4 rows.
    __shared__ float s[32][33];
    int kb = blockIdx.x - NB_CVT;
    int j0 = (kb % (D_OUT / 32)) * 32;     // d_out (n)
    int i0 = (kb / (D_OUT / 32)) * 32;     // d_in (k)
    int tx = threadIdx.x & 31, ty0 = (threadIdx.x >> 5) * 4;
#pragma unroll
    for (int e = 0; e < 4; e++) {
        int ty = ty0 + e;
        int i = i0 + ty, j = j0 + tx;
        float p0 = 0.f, p1 = 0.f;
#pragma unroll
        for (int r = 0; r < RANK; r++) {
            p0 += __ldg(&a0[i * RANK + r]) * __ldg(&b0[r * D_OUT + j]);
            p1 += __ldg(&a1[i * RANK + r]) * __ldg(&b1[r * D_OUT + j]);
        }
        s[ty][tx] = W[(size_t)i * D_OUT + j] + (1.0f / 256.0f) * p0 * p1;
    }
    __syncthreads();
#pragma unroll
    for (int e = 0; e < 4; e++) {
        int ty = ty0 + e;
        // transposed write: value at (i0+tx, j0+ty) -> g_k16[(j0+ty)][i0+tx]
        g_k16[(size_t)(j0 + ty) * D_IN + (i0 + tx)] = __float2half_rn(s[tx][ty]);
    }
}

// ---------------------------------------------------------------------------
// fp16 GEMM: out[BM=128 x BN=128] = x @ K^T + bias  (R7/R12/R13/R14 verified)
// 128 threads = 4 warps (2M x 2N), 64x64 warp tiles, 2 CTAs/SM.
// BK=64, 3-stage cp.async pipeline + register fragment double-buffering.
// ---------------------------------------------------------------------------
constexpr int BM = 128, BN = 128, BK = 64;
constexpr int NT_M = M_TOT / BM;    // 128
constexpr int NT_N = D_OUT / BN;    // 32
constexpr int NKIT = D_IN / BK;     // 64
constexpr int GROUP = 8;

constexpr int XT_SZ = BM * 128;     // 16 KB
constexpr int KT_SZ = BN * 128;     // 16 KB
constexpr int STAGE_SZ = XT_SZ + KT_SZ;   // 32 KB
constexpr int NSTAGE = 3;
constexpr int SMEM_BYTES = NSTAGE * STAGE_SZ;   // 96 KB

struct Frags {
    uint32_t a[4][4];
    uint32_t b[8][2];
};

__global__ void __launch_bounds__(128, 2)
gemm_kernel(float* __restrict__ out, const float* __restrict__ bias) {
    extern __shared__ char smem[];
    const uint32_t sb = smem_u32(smem);
    const int tid = threadIdx.x;
    const int wid = tid >> 5, lane = tid & 31;
    const int wm = (wid >> 1) * 64;   // 2 warps in M
    const int wn = (wid & 1) * 64;    // 2 warps in N

    const int gsz = GROUP * NT_N;          // 256
    const int grp = blockIdx.x / gsz, rem = blockIdx.x % gsz;
    const int m0 = (grp * GROUP + (rem % GROUP)) * BM;
    const int n0 = (rem / GROUP) * BN;

    const __half* x_base = g_x16 + (size_t)m0 * D_IN;
    const __half* k_base = g_k16 + (size_t)n0 * D_IN;

    float acc[4][8][4];
#pragma unroll
    for (int mi = 0; mi < 4; mi++)
#pragma unroll
        for (int ni = 0; ni < 8; ni++)
#pragma unroll
            for (int e = 0; e < 4; e++) acc[mi][ni][e] = 0.f;

    auto load_tile = [&](int it, int buf) {
        const uint32_t st = sb + buf * STAGE_SZ;
        const int k0 = it * BK;
#pragma unroll
        for (int jc = 0; jc < 8; jc++) {
            int c = tid + jc * 128;
            int row = c >> 3, cc = c & 7;
            cp16(st + swz((uint32_t)(row * 128 + cc * 16)),
                 x_base + (size_t)row * D_IN + k0 + cc * 8);
        }
#pragma unroll
        for (int jc = 0; jc < 8; jc++) {
            int c = tid + jc * 128;
            int row = c >> 3, cc = c & 7;
            cp16(st + XT_SZ + swz((uint32_t)(row * 128 + cc * 16)),
                 k_base + (size_t)row * D_IN + k0 + cc * 8);
        }
        CP_COMMIT();
    };

    const int a_row = lane & 15;
    const int a_kb  = (lane >> 4) << 4;
    const int b_row = (lane & 7) + ((lane >> 4) << 3);
    const int b_kb  = ((lane >> 3) & 1) << 4;

    auto load_frags = [&](Frags& f, int buf, int ks) {
        const uint32_t sX = sb + buf * STAGE_SZ;
        const uint32_t sK = sX + XT_SZ;
        const uint32_t kbase = (uint32_t)ks * 32;
#pragma unroll
        for (int g = 0; g < 4; g++) {
            uint32_t off = swz((uint32_t)((wn + g * 16 + b_row) * 128) + kbase + b_kb);
            uint32_t r0, r1, r2, r3;
            ldsm_x4(r0, r1, r2, r3, sK + off);
            f.b[g * 2][0] = r0;     f.b[g * 2][1] = r1;
            f.b[g * 2 + 1][0] = r2; f.b[g * 2 + 1][1] = r3;
        }
#pragma unroll
        for (int mi = 0; mi < 4; mi++) {
            uint32_t off = swz((uint32_t)((wm + mi * 16 + a_row) * 128) + kbase + a_kb);
            ldsm_x4(f.a[mi][0], f.a[mi][1], f.a[mi][2], f.a[mi][3], sX + off);
        }
    };

    auto mma_frags = [&](const Frags& f) {
#pragma unroll
        for (int mi = 0; mi < 4; mi++)
#pragma unroll
            for (int ni = 0; ni < 8; ni++)
                mma16816(acc[mi][ni], f.a[mi], f.b[ni]);
    };

    // Prologue: 2 stages in flight; frags for (tile 0, ks 0)
    load_tile(0, 0);
    load_tile(1, 1);
    CP_WAIT1();
    __syncthreads();

    Frags f0, f1;
    load_frags(f0, 0, 0);

#pragma unroll 1
    for (int it = 0; it < NKIT; it++) {
        const int buf = it % NSTAGE;
        if (it + 2 < NKIT) load_tile(it + 2, (it + 2) % NSTAGE);
        else CP_COMMIT();   // keep group counting uniform

        load_frags(f1, buf, 1);  mma_frags(f0);
        load_frags(f0, buf, 2);  mma_frags(f1);
        load_frags(f1, buf, 3);  mma_frags(f0);

        if (it + 1 < NKIT) {
            CP_WAIT1();          // tile it+1 resident
            __syncthreads();     // all warps done with stage reads; cp visible
            load_frags(f0, (it + 1) % NSTAGE, 0);
            mma_frags(f1);
        } else {
            mma_frags(f1);
        }
    }

    // Epilogue: fused bias, float2 stores
    const int gr = lane >> 2, q = lane & 3;
#pragma unroll
    for (int ni = 0; ni < 8; ni++) {
        int col = n0 + wn + ni * 8 + q * 2;
        float2 bv = *reinterpret_cast<const float2*>(&bias[col]);
#pragma unroll
        for (int mi = 0; mi < 4; mi++) {
            int row0 = m0 + wm + mi * 16 + gr;
            float2 v0 = {acc[mi][ni][0] + bv.x, acc[mi][ni][1] + bv.y};
            float2 v1 = {acc[mi][ni][2] + bv.x, acc[mi][ni][3] + bv.y};
            *reinterpret_cast<float2*>(&out[(size_t)row0 * D_OUT + col]) = v0;
            *reinterpret_cast<float2*>(&out[(size_t)(row0 + 8) * D_OUT + col]) = v1;
        }
    }
}

// ---------------------------------------------------------------------------
// Entry
// ---------------------------------------------------------------------------
extern "C" void kernel_launch(void* const* d_in, const int* in_sizes, int n_in,
                              void* d_out, int out_size) {
    const float* x    = (const float*)d_in[0];
    const float* W    = (const float*)d_in[1];
    const float* bias = (const float*)d_in[2];
    const float* a0   = (const float*)d_in[3];
    const float* b0   = (const float*)d_in[4];
    const float* a1   = (const float*)d_in[5];
    const float* b1   = (const float*)d_in[6];
    float* out = (float*)d_out;
    (void)in_sizes; (void)n_in; (void)out_size;

    cudaFuncSetAttribute(gemm_kernel,
                         cudaFuncAttributeMaxDynamicSharedMemorySize, SMEM_BYTES);

    aux_kernel<<<NB_CVT + NB_K, 256>>>((const float4*)x, W, a0, b0, a1, b1);
    gemm_kernel<<<NT_M * NT_N, 128, SMEM_BYTES>>>(out, bias);
}

// round 16
// speedup vs baseline: 1.5333x; 1.5333x over previous
#include <cuda_runtime.h>
#include <cuda_fp16.h>
#include <cstdint>

#define D_IN  4096
#define D_OUT 4096
#define M_TOT 16384
constexpr int RANK = 16;

// ---------------------------------------------------------------------------
// Scratch: fp16 copies of x and K^T
// ---------------------------------------------------------------------------
__device__ __half g_x16[(size_t)M_TOT * D_IN];     // [M,K] K-contig, 128 MB
__device__ __half g_k16[(size_t)D_OUT * D_IN];     // K^T [N,K] K-contig, 32 MB

// ---------------------------------------------------------------------------
// Helpers
// ---------------------------------------------------------------------------
__device__ __forceinline__ uint32_t smem_u32(const void* p) {
    return (uint32_t)__cvta_generic_to_shared(p);
}
__device__ __forceinline__ void cp16(uint32_t s, const void* g) {
    asm volatile("cp.async.cg.shared.global [%0], [%1], 16;\n" :: "r"(s), "l"(g));
}
#define CP_COMMIT() asm volatile("cp.async.commit_group;\n")
#define CP_WAIT1()  asm volatile("cp.async.wait_group 1;\n")

__device__ __forceinline__ void ldsm_x4(uint32_t& r0, uint32_t& r1, uint32_t& r2,
                                        uint32_t& r3, uint32_t a) {
    asm volatile("ldmatrix.sync.aligned.m8n8.x4.shared.b16 {%0,%1,%2,%3}, [%4];\n"
                 : "=r"(r0), "=r"(r1), "=r"(r2), "=r"(r3) : "r"(a));
}
__device__ __forceinline__ void mma16816(float* c, const uint32_t* a, const uint32_t* b) {
    asm volatile(
        "mma.sync.aligned.m16n8k16.row.col.f32.f16.f16.f32 "
        "{%0,%1,%2,%3}, {%4,%5,%6,%7}, {%8,%9}, {%0,%1,%2,%3};\n"
        : "+f"(c[0]), "+f"(c[1]), "+f"(c[2]), "+f"(c[3])
        : "r"(a[0]), "r"(a[1]), "r"(a[2]), "r"(a[3]), "r"(b[0]), "r"(b[1]));
}

// SW128 swizzle on byte offsets within a tile (128-byte rows)
__device__ __forceinline__ uint32_t swz(uint32_t b) { return b ^ ((b >> 3) & 0x70); }

// ---------------------------------------------------------------------------
// Combined aux kernel: one launch, blockIdx-partitioned.
//   blocks [0, NB_CVT)           : x fp32 -> fp16 (8 elems/thread)
//   blocks [NB_CVT, NB_CVT+NB_K) : build K^T fp16 (32x32 transpose tiles)
// Both DRAM-bound; one launch lets the two phases' waves overlap.
// ---------------------------------------------------------------------------
constexpr int NB_CVT = (int)(((size_t)M_TOT * D_IN) / 8 / 256);   // 32768
constexpr int NB_K   = (D_OUT / 32) * (D_IN / 32);                // 16384

__global__ void __launch_bounds__(256)
aux_kernel(const float4* __restrict__ x, const float* __restrict__ W,
           const float* __restrict__ a0, const float* __restrict__ b0,
           const float* __restrict__ a1, const float* __restrict__ b1) {
    if (blockIdx.x < NB_CVT) {
        size_t i = (size_t)blockIdx.x * 256 + threadIdx.x;
        float4 v0 = x[2 * i], v1 = x[2 * i + 1];
        union { __half h[8]; uint4 u; } o;
        o.h[0] = __float2half_rn(v0.x); o.h[1] = __float2half_rn(v0.y);
        o.h[2] = __float2half_rn(v0.z); o.h[3] = __float2half_rn(v0.w);
        o.h[4] = __float2half_rn(v1.x); o.h[5] = __float2half_rn(v1.y);
        o.h[6] = __float2half_rn(v1.z); o.h[7] = __float2half_rn(v1.w);
        reinterpret_cast<uint4*>(g_x16)[i] = o.u;
        return;
    }
    // build_k: K = W + (1/256)(a0@b0)⊙(a1@b1), transposed into g_k16[n][k].
    // 256 threads per 32x32 tile, each thread computes 4 rows.
    __shared__ float s[32][33];
    int kb = blockIdx.x - NB_CVT;
    int j0 = (kb % (D_OUT / 32)) * 32;     // d_out (n)
    int i0 = (kb / (D_OUT / 32)) * 32;     // d_in (k)
    int tx = threadIdx.x & 31, ty0 = (threadIdx.x >> 5) * 4;
#pragma unroll
    for (int e = 0; e < 4; e++) {
        int ty = ty0 + e;
        int i = i0 + ty, j = j0 + tx;
        float p0 = 0.f, p1 = 0.f;
#pragma unroll
        for (int r = 0; r < RANK; r++) {
            p0 += __ldg(&a0[i * RANK + r]) * __ldg(&b0[r * D_OUT + j]);
            p1 += __ldg(&a1[i * RANK + r]) * __ldg(&b1[r * D_OUT + j]);
        }
        s[ty][tx] = W[(size_t)i * D_OUT + j] + (1.0f / 256.0f) * p0 * p1;
    }
    __syncthreads();
#pragma unroll
    for (int e = 0; e < 4; e++) {
        int ty = ty0 + e;
        // transposed write: value at (i0+tx, j0+ty) -> g_k16[(j0+ty)][i0+tx]
        g_k16[(size_t)(j0 + ty) * D_IN + (i0 + tx)] = __float2half_rn(s[tx][ty]);
    }
}

// ---------------------------------------------------------------------------
// fp16 GEMM: out[BM=128 x BN=128] = x @ K^T + bias  (R13/R14 verified: 1188us)
// 128 threads = 4 warps (2M x 2N), 64x64 warp tiles, 2 CTAs/SM.
// BK=64, 3-stage cp.async pipeline + register fragment double-buffering.
// ---------------------------------------------------------------------------
constexpr int BM = 128, BN = 128, BK = 64;
constexpr int NT_M = M_TOT / BM;    // 128
constexpr int NT_N = D_OUT / BN;    // 32
constexpr int NKIT = D_IN / BK;     // 64
constexpr int GROUP = 8;

constexpr int XT_SZ = BM * 128;     // 16 KB
constexpr int KT_SZ = BN * 128;     // 16 KB
constexpr int STAGE_SZ = XT_SZ + KT_SZ;   // 32 KB
constexpr int NSTAGE = 3;
constexpr int SMEM_BYTES = NSTAGE * STAGE_SZ;   // 96 KB

struct Frags {
    uint32_t a[4][4];
    uint32_t b[8][2];
};

__global__ void __launch_bounds__(128, 2)
gemm_kernel(float* __restrict__ out, const float* __restrict__ bias) {
    extern __shared__ char smem[];
    const uint32_t sb = smem_u32(smem);
    const int tid = threadIdx.x;
    const int wid = tid >> 5, lane = tid & 31;
    const int wm = (wid >> 1) * 64;   // 2 warps in M
    const int wn = (wid & 1) * 64;    // 2 warps in N

    const int gsz = GROUP * NT_N;          // 256
    const int grp = blockIdx.x / gsz, rem = blockIdx.x % gsz;
    const int m0 = (grp * GROUP + (rem % GROUP)) * BM;
    const int n0 = (rem / GROUP) * BN;

    const __half* x_base = g_x16 + (size_t)m0 * D_IN;
    const __half* k_base = g_k16 + (size_t)n0 * D_IN;

    float acc[4][8][4];
#pragma unroll
    for (int mi = 0; mi < 4; mi++)
#pragma unroll
        for (int ni = 0; ni < 8; ni++)
#pragma unroll
            for (int e = 0; e < 4; e++) acc[mi][ni][e] = 0.f;

    auto load_tile = [&](int it, int buf) {
        const uint32_t st = sb + buf * STAGE_SZ;
        const int k0 = it * BK;
#pragma unroll
        for (int jc = 0; jc < 8; jc++) {
            int c = tid + jc * 128;
            int row = c >> 3, cc = c & 7;
            cp16(st + swz((uint32_t)(row * 128 + cc * 16)),
                 x_base + (size_t)row * D_IN + k0 + cc * 8);
        }
#pragma unroll
        for (int jc = 0; jc < 8; jc++) {
            int c = tid + jc * 128;
            int row = c >> 3, cc = c & 7;
            cp16(st + XT_SZ + swz((uint32_t)(row * 128 + cc * 16)),
                 k_base + (size_t)row * D_IN + k0 + cc * 8);
        }
        CP_COMMIT();
    };

    const int a_row = lane & 15;
    const int a_kb  = (lane >> 4) << 4;
    const int b_row = (lane & 7) + ((lane >> 4) << 3);
    const int b_kb  = ((lane >> 3) & 1) << 4;

    auto load_frags = [&](Frags& f, int buf, int ks) {
        const uint32_t sX = sb + buf * STAGE_SZ;
        const uint32_t sK = sX + XT_SZ;
        const uint32_t kbase = (uint32_t)ks * 32;
#pragma unroll
        for (int g = 0; g < 4; g++) {
            uint32_t off = swz((uint32_t)((wn + g * 16 + b_row) * 128) + kbase + b_kb);
            uint32_t r0, r1, r2, r3;
            ldsm_x4(r0, r1, r2, r3, sK + off);
            f.b[g * 2][0] = r0;     f.b[g * 2][1] = r1;
            f.b[g * 2 + 1][0] = r2; f.b[g * 2 + 1][1] = r3;
        }
#pragma unroll
        for (int mi = 0; mi < 4; mi++) {
            uint32_t off = swz((uint32_t)((wm + mi * 16 + a_row) * 128) + kbase + a_kb);
            ldsm_x4(f.a[mi][0], f.a[mi][1], f.a[mi][2], f.a[mi][3], sX + off);
        }
    };

    auto mma_frags = [&](const Frags& f) {
#pragma unroll
        for (int mi = 0; mi < 4; mi++)
#pragma unroll
            for (int ni = 0; ni < 8; ni++)
                mma16816(acc[mi][ni], f.a[mi], f.b[ni]);
    };

    // Prologue: 2 stages in flight; frags for (tile 0, ks 0)
    load_tile(0, 0);
    load_tile(1, 1);
    CP_WAIT1();
    __syncthreads();

    Frags f0, f1;
    load_frags(f0, 0, 0);

#pragma unroll 1
    for (int it = 0; it < NKIT; it++) {
        const int buf = it % NSTAGE;
        if (it + 2 < NKIT) load_tile(it + 2, (it + 2) % NSTAGE);
        else CP_COMMIT();   // keep group counting uniform

        load_frags(f1, buf, 1);  mma_frags(f0);
        load_frags(f0, buf, 2);  mma_frags(f1);
        load_frags(f1, buf, 3);  mma_frags(f0);

        if (it + 1 < NKIT) {
            CP_WAIT1();          // tile it+1 resident
            __syncthreads();     // all warps done with stage reads; cp visible
            load_frags(f0, (it + 1) % NSTAGE, 0);
            mma_frags(f1);
        } else {
            mma_frags(f1);
        }
    }

    // Epilogue: fused bias, float2 stores
    const int gr = lane >> 2, q = lane & 3;
#pragma unroll
    for (int ni = 0; ni < 8; ni++) {
        int col = n0 + wn + ni * 8 + q * 2;
        float2 bv = *reinterpret_cast<const float2*>(&bias[col]);
#pragma unroll
        for (int mi = 0; mi < 4; mi++) {
            int row0 = m0 + wm + mi * 16 + gr;
            float2 v0 = {acc[mi][ni][0] + bv.x, acc[mi][ni][1] + bv.y};
            float2 v1 = {acc[mi][ni][2] + bv.x, acc[mi][ni][3] + bv.y};
            *reinterpret_cast<float2*>(&out[(size_t)row0 * D_OUT + col]) = v0;
            *reinterpret_cast<float2*>(&out[(size_t)(row0 + 8) * D_OUT + col]) = v1;
        }
    }
}

// ---------------------------------------------------------------------------
// Entry
// ---------------------------------------------------------------------------
extern "C" void kernel_launch(void* const* d_in, const int* in_sizes, int n_in,
                              void* d_out, int out_size) {
    const float* x    = (const float*)d_in[0];
    const float* W    = (const float*)d_in[1];
    const float* bias = (const float*)d_in[2];
    const float* a0   = (const float*)d_in[3];
    const float* b0   = (const float*)d_in[4];
    const float* a1   = (const float*)d_in[5];
    const float* b1   = (const float*)d_in[6];
    float* out = (float*)d_out;
    (void)in_sizes; (void)n_in; (void)out_size;

    cudaFuncSetAttribute(gemm_kernel,
                         cudaFuncAttributeMaxDynamicSharedMemorySize, SMEM_BYTES);

    aux_kernel<<<NB_CVT + NB_K, 256>>>((const float4*)x, W, a0, b0, a1, b1);
    gemm_kernel<<<NT_M * NT_N, 128, SMEM_BYTES>>>(out, bias);
}